// round 3
// baseline (speedup 1.0000x reference)
#include <cuda_runtime.h>
#include <cstdint>

#define N_NODES 100000
#define N_EDGES 1600000
#define D 128

// Scratch (allocation-free rule: __device__ globals)
__device__ float g_h[(size_t)N_NODES * D];   // h = x @ W
__device__ float g_x[(size_t)N_NODES * D];   // aggregated output (layers 0,1)
__device__ float g_deg[N_NODES];
__device__ float g_dinv[N_NODES];
__device__ int   g_is64;                     // edge_index dtype flag
__device__ int   g_erow[N_EDGES];            // decoded int32 source nodes
__device__ int   g_ecol[N_EDGES];            // decoded int32 target nodes

// ---------------------------------------------------------------------------
// Edge index dtype detection + decode.
// If the buffer holds int64 values < 2^31, every odd 32-bit word (high half)
// is zero. If it holds int32 node ids, odd words are random indices.
// ---------------------------------------------------------------------------
__global__ void k_detect(const unsigned int* __restrict__ buf) {
    __shared__ unsigned int acc;
    if (threadIdx.x == 0) acc = 0u;
    __syncthreads();
    unsigned int local = 0u;
    // First 8192 words exist in both layouts (int32: 3.2M words total).
    for (int i = threadIdx.x; i < 4096; i += blockDim.x)
        local |= buf[2 * i + 1];
    atomicOr(&acc, local);
    __syncthreads();
    if (threadIdx.x == 0) g_is64 = (acc == 0u) ? 1 : 0;
}

__global__ void k_convert(const void* __restrict__ buf) {
    int e = blockIdx.x * blockDim.x + threadIdx.x;
    if (e >= N_EDGES) return;
    if (g_is64) {
        const long long* p = (const long long*)buf;
        g_erow[e] = (int)p[e];
        g_ecol[e] = (int)p[e + N_EDGES];
    } else {
        const int* p = (const int*)buf;
        g_erow[e] = p[e];
        g_ecol[e] = p[e + N_EDGES];
    }
}

// ---------------------------------------------------------------------------
// Degrees: deg[i] = 1 (self loop) + #edges with col==i;  dinv = rsqrt(deg)
// ---------------------------------------------------------------------------
__global__ void k_init_deg() {
    int i = blockIdx.x * blockDim.x + threadIdx.x;
    if (i < N_NODES) g_deg[i] = 1.0f;
}

__global__ void k_count_deg() {
    int e = blockIdx.x * blockDim.x + threadIdx.x;
    if (e < N_EDGES) atomicAdd(&g_deg[g_ecol[e]], 1.0f);
}

__global__ void k_dinv() {
    int i = blockIdx.x * blockDim.x + threadIdx.x;
    if (i < N_NODES) g_dinv[i] = rsqrtf(g_deg[i]);   // deg >= 1 always
}

// ---------------------------------------------------------------------------
// GEMM: H[M,128] = act(A[M,128]) @ W[128,128]
// Fused epilogue: X[row][c] = bias[c] + H[row][c] * dinv[row]^2   (self loop)
// Tile: 64 rows x 128 cols per block, 256 threads, 8x4 micro-tile per thread.
// ---------------------------------------------------------------------------
template<bool RELU_IN, bool FROM_GX>
__global__ void __launch_bounds__(256, 3)
k_gemm_fused(const float* __restrict__ Ain, const float* __restrict__ W,
             const float* __restrict__ bias,
             float* __restrict__ out, int use_out) {
    __shared__ float Ws[64][D];   // 32 KB: k-half of W, all 128 output cols
    __shared__ float Xs[64][64];  // 16 KB: 64 rows x k-half

    const int tid = threadIdx.x;
    const int tx = tid & 31;      // output col group: cols tx*4 .. tx*4+3
    const int ty = tid >> 5;      // row group: rows ty*8 .. ty*8+7
    const int row0 = blockIdx.x * 64;

    const float* A = FROM_GX ? g_x : Ain;
    float* X = use_out ? out : g_x;

    float acc[8][4];
#pragma unroll
    for (int i = 0; i < 8; i++)
#pragma unroll
        for (int j = 0; j < 4; j++) acc[i][j] = 0.0f;

    const float4* A4 = (const float4*)A;   // 32 float4 per row
    const float4* W4 = (const float4*)W;

#pragma unroll
    for (int kk = 0; kk < 2; kk++) {
        __syncthreads();
        // Load W half: rows kk*64 .. +63, 128 cols = 2048 float4, 8 per thread
#pragma unroll
        for (int i = 0; i < 8; i++) {
            int idx = tid + i * 256;
            int r = idx >> 5, c = idx & 31;
            ((float4*)&Ws[r][0])[c] = W4[(kk * 64 + r) * 32 + c];
        }
        // Load X half: 64 rows x 64 k = 1024 float4, 4 per thread
#pragma unroll
        for (int i = 0; i < 4; i++) {
            int idx = tid + i * 256;
            int r = idx >> 4, c = idx & 15;   // 16 float4 per row-half
            int gr = row0 + r;
            float4 v = make_float4(0.f, 0.f, 0.f, 0.f);
            if (gr < N_NODES) v = A4[(size_t)gr * 32 + kk * 16 + c];
            if (RELU_IN) {
                v.x = fmaxf(v.x, 0.f); v.y = fmaxf(v.y, 0.f);
                v.z = fmaxf(v.z, 0.f); v.w = fmaxf(v.w, 0.f);
            }
            ((float4*)&Xs[r][0])[c] = v;
        }
        __syncthreads();

#pragma unroll
        for (int k = 0; k < 64; k++) {
            float4 w = ((const float4*)&Ws[k][0])[tx];
#pragma unroll
            for (int i = 0; i < 8; i++) {
                float a = Xs[ty * 8 + i][k];
                acc[i][0] = fmaf(a, w.x, acc[i][0]);
                acc[i][1] = fmaf(a, w.y, acc[i][1]);
                acc[i][2] = fmaf(a, w.z, acc[i][2]);
                acc[i][3] = fmaf(a, w.w, acc[i][3]);
            }
        }
    }

    // Epilogue: write H and X = bias + H * dinv^2
    float4 bb = ((const float4*)bias)[tx];
#pragma unroll
    for (int i = 0; i < 8; i++) {
        int row = row0 + ty * 8 + i;
        if (row >= N_NODES) continue;
        float s = g_dinv[row]; s = s * s;
        float4 h = make_float4(acc[i][0], acc[i][1], acc[i][2], acc[i][3]);
        ((float4*)&g_h[(size_t)row * D])[tx] = h;
        float4 x = make_float4(bb.x + h.x * s, bb.y + h.y * s,
                               bb.z + h.z * s, bb.w + h.w * s);
        ((float4*)&X[(size_t)row * D])[tx] = x;
    }
}

// ---------------------------------------------------------------------------
// Edge scatter: one warp per edge.
// dst[col] += h[row] * (dinv[row]*dinv[col]),  4 floats per lane (scalar RED).
// ---------------------------------------------------------------------------
__global__ void __launch_bounds__(256)
k_scatter(float* __restrict__ out, int use_out) {
    int e = (blockIdx.x * blockDim.x + threadIdx.x) >> 5;
    int lane = threadIdx.x & 31;
    if (e >= N_EDGES) return;
    float* base = use_out ? out : g_x;
    int r = g_erow[e];
    int c = g_ecol[e];
    float norm = g_dinv[r] * g_dinv[c];
    float4 h = ((const float4*)(g_h + (size_t)r * D))[lane];
    float* dst = base + (size_t)c * D + lane * 4;
    atomicAdd(dst + 0, h.x * norm);
    atomicAdd(dst + 1, h.y * norm);
    atomicAdd(dst + 2, h.z * norm);
    atomicAdd(dst + 3, h.w * norm);
}

// ---------------------------------------------------------------------------
// Final in-place ReLU on d_out
// ---------------------------------------------------------------------------
__global__ void k_relu_inplace(float* __restrict__ out) {
    int idx = blockIdx.x * blockDim.x + threadIdx.x;   // float4 index
    if (idx < N_NODES * (D / 4)) {
        float4 v = ((float4*)out)[idx];
        v.x = fmaxf(v.x, 0.f); v.y = fmaxf(v.y, 0.f);
        v.z = fmaxf(v.z, 0.f); v.w = fmaxf(v.w, 0.f);
        ((float4*)out)[idx] = v;
    }
}

// ---------------------------------------------------------------------------
// Launch
// inputs: d_in[0] edge_index [2, E] int (32 or 64 — detected on device),
//         d_in[1] emb [N, D] f32, d_in[2] Ws [L, D, D] f32, d_in[3] bs [L, D]
// output: [N, D] f32
// ---------------------------------------------------------------------------
extern "C" void kernel_launch(void* const* d_in, const int* in_sizes, int n_in,
                              void* d_out, int out_size) {
    const void* edge = d_in[0];
    const float* emb = (const float*)d_in[1];
    const float* Ws  = (const float*)d_in[2];
    const float* bs  = (const float*)d_in[3];
    float* out = (float*)d_out;

    // Decode edge index (dtype-agnostic)
    k_detect<<<1, 256>>>((const unsigned int*)edge);
    k_convert<<<(N_EDGES + 255) / 256, 256>>>(edge);

    // Degrees + normalization
    k_init_deg<<<(N_NODES + 255) / 256, 256>>>();
    k_count_deg<<<(N_EDGES + 255) / 256, 256>>>();
    k_dinv<<<(N_NODES + 255) / 256, 256>>>();

    const int gemm_blocks = (N_NODES + 63) / 64;
    const int scat_blocks = (int)(((long long)N_EDGES * 32 + 255) / 256);

    // Layer 0: input emb (no relu), aggregate into g_x
    k_gemm_fused<false, false><<<gemm_blocks, 256>>>(emb, Ws + 0 * D * D,
                                                     bs + 0 * D, out, 0);
    k_scatter<<<scat_blocks, 256>>>(out, 0);

    // Layer 1: input relu(g_x), aggregate into g_x
    k_gemm_fused<true, true><<<gemm_blocks, 256>>>(nullptr, Ws + 1 * D * D,
                                                   bs + 1 * D, out, 0);
    k_scatter<<<scat_blocks, 256>>>(out, 0);

    // Layer 2: input relu(g_x), aggregate directly into d_out, final relu
    k_gemm_fused<true, true><<<gemm_blocks, 256>>>(nullptr, Ws + 2 * D * D,
                                                   bs + 2 * D, out, 1);
    k_scatter<<<scat_blocks, 256>>>(out, 1);
    k_relu_inplace<<<(N_NODES * (D / 4) + 255) / 256, 256>>>(out);
}

// round 4
// speedup vs baseline: 3.2158x; 3.2158x over previous
#include <cuda_runtime.h>
#include <cstdint>

#define N_NODES 100000
#define N_EDGES 1600000
#define D 128
#define SCAN_B 1024
#define N_SCAN_BLOCKS ((N_NODES + SCAN_B - 1) / SCAN_B)   // 98

// Scratch (allocation-free rule: __device__ globals)
__device__ float g_h[(size_t)N_NODES * D];   // h = x @ W
__device__ float g_x[(size_t)N_NODES * D];   // layer activations
__device__ float g_dinv[N_NODES];
__device__ int   g_is64;                     // edge_index dtype flag
__device__ int   g_erow[N_EDGES];            // decoded int32 source nodes
__device__ int   g_ecol[N_EDGES];            // decoded int32 target nodes
__device__ int   g_cnt[N_NODES];             // in-degree (excl. self loop)
__device__ int   g_rowptr[N_NODES + 1];      // CSR row pointers (by target)
__device__ int   g_cursor[N_NODES];          // fill cursors
__device__ int   g_src[N_EDGES];             // CSR: source node per slot
__device__ int   g_bsum[N_SCAN_BLOCKS];      // scan block sums

// ---------------------------------------------------------------------------
// Edge index dtype detection + decode.
// int64 values < 2^31 => every odd 32-bit word (high half) is zero.
// ---------------------------------------------------------------------------
__global__ void k_detect(const unsigned int* __restrict__ buf) {
    __shared__ unsigned int acc;
    if (threadIdx.x == 0) acc = 0u;
    __syncthreads();
    unsigned int local = 0u;
    for (int i = threadIdx.x; i < 4096; i += blockDim.x)
        local |= buf[2 * i + 1];
    atomicOr(&acc, local);
    __syncthreads();
    if (threadIdx.x == 0) g_is64 = (acc == 0u) ? 1 : 0;
}

__global__ void k_convert(const void* __restrict__ buf) {
    int e = blockIdx.x * blockDim.x + threadIdx.x;
    if (e >= N_EDGES) return;
    if (g_is64) {
        const long long* p = (const long long*)buf;
        g_erow[e] = (int)p[e];
        g_ecol[e] = (int)p[e + N_EDGES];
    } else {
        const int* p = (const int*)buf;
        g_erow[e] = p[e];
        g_ecol[e] = p[e + N_EDGES];
    }
}

// ---------------------------------------------------------------------------
// CSR build: zero -> histogram -> dinv -> scan -> fill
// ---------------------------------------------------------------------------
__global__ void k_zero() {
    int i = blockIdx.x * blockDim.x + threadIdx.x;
    if (i < N_NODES) { g_cnt[i] = 0; g_cursor[i] = 0; }
}

__global__ void k_hist() {
    int e = blockIdx.x * blockDim.x + threadIdx.x;
    if (e < N_EDGES) atomicAdd(&g_cnt[g_ecol[e]], 1);
}

__global__ void k_dinv() {
    int i = blockIdx.x * blockDim.x + threadIdx.x;
    if (i < N_NODES) g_dinv[i] = rsqrtf(1.0f + (float)g_cnt[i]);
}

__global__ void __launch_bounds__(SCAN_B)
k_scan1() {
    __shared__ int s[SCAN_B];
    int i = blockIdx.x * SCAN_B + threadIdx.x;
    int v = (i < N_NODES) ? g_cnt[i] : 0;
    s[threadIdx.x] = v;
    __syncthreads();
#pragma unroll
    for (int off = 1; off < SCAN_B; off <<= 1) {
        int t = (threadIdx.x >= off) ? s[threadIdx.x - off] : 0;
        __syncthreads();
        s[threadIdx.x] += t;
        __syncthreads();
    }
    if (i < N_NODES) g_rowptr[i] = s[threadIdx.x] - v;   // exclusive in block
    if (threadIdx.x == SCAN_B - 1) g_bsum[blockIdx.x] = s[SCAN_B - 1];
}

__global__ void k_scan2() {
    if (threadIdx.x == 0) {
        int run = 0;
        for (int b = 0; b < N_SCAN_BLOCKS; b++) {
            int t = g_bsum[b];
            g_bsum[b] = run;
            run += t;
        }
        g_rowptr[N_NODES] = N_EDGES;
    }
}

__global__ void k_scan3() {
    int i = blockIdx.x * blockDim.x + threadIdx.x;
    if (i < N_NODES) g_rowptr[i] += g_bsum[i / SCAN_B];
}

__global__ void k_fill() {
    int e = blockIdx.x * blockDim.x + threadIdx.x;
    if (e >= N_EDGES) return;
    int c = g_ecol[e];
    int pos = atomicAdd(&g_cursor[c], 1);
    g_src[g_rowptr[c] + pos] = g_erow[e];
}

// ---------------------------------------------------------------------------
// GEMM: g_h[M,128] = A[M,128] @ W[128,128]   (A already ReLU'd upstream)
// Tile: 64 rows x 128 cols per block, 256 threads, 8x4 micro-tile per thread.
// ---------------------------------------------------------------------------
template<bool FROM_GX>
__global__ void __launch_bounds__(256, 3)
k_gemm(const float* __restrict__ Ain, const float* __restrict__ W) {
    __shared__ float Ws[64][D];   // 32 KB
    __shared__ float Xs[64][64];  // 16 KB

    const int tid = threadIdx.x;
    const int tx = tid & 31;
    const int ty = tid >> 5;
    const int row0 = blockIdx.x * 64;

    const float* A = FROM_GX ? g_x : Ain;

    float acc[8][4];
#pragma unroll
    for (int i = 0; i < 8; i++)
#pragma unroll
        for (int j = 0; j < 4; j++) acc[i][j] = 0.0f;

    const float4* A4 = (const float4*)A;
    const float4* W4 = (const float4*)W;

#pragma unroll
    for (int kk = 0; kk < 2; kk++) {
        __syncthreads();
#pragma unroll
        for (int i = 0; i < 8; i++) {
            int idx = tid + i * 256;
            int r = idx >> 5, c = idx & 31;
            ((float4*)&Ws[r][0])[c] = W4[(kk * 64 + r) * 32 + c];
        }
#pragma unroll
        for (int i = 0; i < 4; i++) {
            int idx = tid + i * 256;
            int r = idx >> 4, c = idx & 15;
            int gr = row0 + r;
            float4 v = make_float4(0.f, 0.f, 0.f, 0.f);
            if (gr < N_NODES) v = A4[(size_t)gr * 32 + kk * 16 + c];
            ((float4*)&Xs[r][0])[c] = v;
        }
        __syncthreads();

#pragma unroll
        for (int k = 0; k < 64; k++) {
            float4 w = ((const float4*)&Ws[k][0])[tx];
#pragma unroll
            for (int i = 0; i < 8; i++) {
                float a = Xs[ty * 8 + i][k];
                acc[i][0] = fmaf(a, w.x, acc[i][0]);
                acc[i][1] = fmaf(a, w.y, acc[i][1]);
                acc[i][2] = fmaf(a, w.z, acc[i][2]);
                acc[i][3] = fmaf(a, w.w, acc[i][3]);
            }
        }
    }

#pragma unroll
    for (int i = 0; i < 8; i++) {
        int row = row0 + ty * 8 + i;
        if (row >= N_NODES) continue;
        ((float4*)&g_h[(size_t)row * D])[tx] =
            make_float4(acc[i][0], acc[i][1], acc[i][2], acc[i][3]);
    }
}

// ---------------------------------------------------------------------------
// Aggregation (gather, no atomics): one warp per target node.
// x[c] = relu( bias + dinv[c]^2 * h[c] + sum_{r in CSR(c)} dinv[r]*dinv[c]*h[r] )
// Lanes batch-load 32 edge srcs + dinv, then shuffle through them so the only
// per-edge dependent loads are the independent h-row gathers (high MLP).
// ---------------------------------------------------------------------------
__global__ void __launch_bounds__(256)
k_aggregate(const float* __restrict__ bias, float* __restrict__ out,
            int use_out) {
    int node = (blockIdx.x * blockDim.x + threadIdx.x) >> 5;
    int lane = threadIdx.x & 31;
    if (node >= N_NODES) return;

    float* dst = use_out ? out : g_x;
    float dinv_c = g_dinv[node];
    float s = dinv_c * dinv_c;

    float4 bb = ((const float4*)bias)[lane];
    float4 hself = ((const float4*)(g_h + (size_t)node * D))[lane];
    float4 acc = make_float4(fmaf(hself.x, s, bb.x), fmaf(hself.y, s, bb.y),
                             fmaf(hself.z, s, bb.z), fmaf(hself.w, s, bb.w));

    int beg = g_rowptr[node];
    int end = g_rowptr[node + 1];
    for (int base = beg; base < end; base += 32) {
        int j = base + lane;
        int r = 0;
        float dr = 0.0f;
        if (j < end) {
            r = g_src[j];
            dr = g_dinv[r];
        }
        int cnt = min(32, end - base);
        for (int k = 0; k < cnt; k++) {
            int rr = __shfl_sync(0xffffffffu, r, k);
            float nn = __shfl_sync(0xffffffffu, dr, k) * dinv_c;
            float4 hv = ((const float4*)(g_h + (size_t)rr * D))[lane];
            acc.x = fmaf(hv.x, nn, acc.x);
            acc.y = fmaf(hv.y, nn, acc.y);
            acc.z = fmaf(hv.z, nn, acc.z);
            acc.w = fmaf(hv.w, nn, acc.w);
        }
    }

    acc.x = fmaxf(acc.x, 0.f); acc.y = fmaxf(acc.y, 0.f);
    acc.z = fmaxf(acc.z, 0.f); acc.w = fmaxf(acc.w, 0.f);
    ((float4*)(dst + (size_t)node * D))[lane] = acc;
}

// ---------------------------------------------------------------------------
// Launch
// ---------------------------------------------------------------------------
extern "C" void kernel_launch(void* const* d_in, const int* in_sizes, int n_in,
                              void* d_out, int out_size) {
    const void* edge = d_in[0];
    const float* emb = (const float*)d_in[1];
    const float* Ws  = (const float*)d_in[2];
    const float* bs  = (const float*)d_in[3];
    float* out = (float*)d_out;

    const int nb_nodes = (N_NODES + 255) / 256;
    const int nb_edges = (N_EDGES + 255) / 256;

    // Decode + CSR build
    k_detect<<<1, 256>>>((const unsigned int*)edge);
    k_convert<<<nb_edges, 256>>>(edge);
    k_zero<<<nb_nodes, 256>>>();
    k_hist<<<nb_edges, 256>>>();
    k_dinv<<<nb_nodes, 256>>>();
    k_scan1<<<N_SCAN_BLOCKS, SCAN_B>>>();
    k_scan2<<<1, 32>>>();
    k_scan3<<<nb_nodes, 256>>>();
    k_fill<<<nb_edges, 256>>>();

    const int gemm_blocks = (N_NODES + 63) / 64;
    const int agg_blocks = (N_NODES * 32 + 255) / 256;   // one warp per node

    // Layer 0
    k_gemm<false><<<gemm_blocks, 256>>>(emb, Ws + 0 * D * D);
    k_aggregate<<<agg_blocks, 256>>>(bs + 0 * D, out, 0);
    // Layer 1
    k_gemm<true><<<gemm_blocks, 256>>>(nullptr, Ws + 1 * D * D);
    k_aggregate<<<agg_blocks, 256>>>(bs + 1 * D, out, 0);
    // Layer 2 -> d_out (ReLU applied in aggregate)
    k_gemm<true><<<gemm_blocks, 256>>>(nullptr, Ws + 2 * D * D);
    k_aggregate<<<agg_blocks, 256>>>(bs + 2 * D, out, 1);
}